// round 8
// baseline (speedup 1.0000x reference)
#include <cuda_runtime.h>
#include <cuda_fp16.h>
#include <cstdint>

// Problem constants
constexpr int N_ROWS = 32768;          // 8*4096
constexpr int D      = 512;
constexpr int KSZ    = 4096;

// Output layout (float32), reference tuple order
constexpr size_t OFF_F    = 0;
constexpr size_t OFF_LOSS = (size_t)N_ROWS * D;
constexpr size_t OFF_K    = OFF_LOSS + 1;
constexpr size_t OFF_ECS  = OFF_K + (size_t)KSZ * D;
constexpr size_t OFF_EMAW = OFF_ECS + KSZ;

// ---------------- device scratch ----------------
__device__ __align__(16) __half g_fhi[(size_t)N_ROWS * D];
__device__ __align__(16) __half g_flo[(size_t)N_ROWS * D];
__device__ __align__(16) __half g_khi[(size_t)KSZ * D];
__device__ __align__(16) __half g_klo[(size_t)KSZ * D];
__device__ float               g_y2[KSZ];
__device__ unsigned long long  g_best[N_ROWS];
__device__ float               g_counts[KSZ];
__device__ float               g_dw[(size_t)KSZ * D];
__device__ double              g_loss;
__device__ double              g_n;

// ---------------- helpers ----------------
__device__ __forceinline__ uint32_t smem_u32(const void* p) {
    uint32_t a;
    asm("{ .reg .u64 t; cvta.to.shared.u64 t, %1; cvt.u32.u64 %0, t; }" : "=r"(a) : "l"(p));
    return a;
}
__device__ __forceinline__ void cp16(uint32_t s, const void* g) {
    asm volatile("cp.async.cg.shared.global [%0], [%1], 16;" :: "r"(s), "l"(g));
}
__device__ __forceinline__ unsigned int fkey(float v) {
    unsigned int b = __float_as_uint(v);
    return (b & 0x80000000u) ? ~b : (b | 0x80000000u);
}
// m16n8k16 fp16 MMA, fp32 accumulate (baseline PTX, tensor pipe)
__device__ __forceinline__ void mma16(float* d, const uint32_t* a, const uint32_t* b) {
    asm volatile("mma.sync.aligned.m16n8k16.row.col.f32.f16.f16.f32 "
                 "{%0,%1,%2,%3}, {%4,%5,%6,%7}, {%8,%9}, {%0,%1,%2,%3};"
                 : "+f"(d[0]), "+f"(d[1]), "+f"(d[2]), "+f"(d[3])
                 : "r"(a[0]), "r"(a[1]), "r"(a[2]), "r"(a[3]), "r"(b[0]), "r"(b[1]));
}

// ---------------- kernel 0: zero scratch ----------------
__global__ void zero_kernel() {
    int i = blockIdx.x * blockDim.x + threadIdx.x;   // covers KSZ*D
    g_dw[i] = 0.0f;
    if (i < KSZ)    g_counts[i] = 0.0f;
    if (i < N_ROWS) g_best[i] = ~0ULL;
    if (i == 0) { g_loss = 0.0; g_n = 0.0; }
}

// ---------------- kernel 1: fp16 hi/lo split ----------------
__global__ void split_kernel(const float* __restrict__ f, const float* __restrict__ Kc) {
    size_t i = (size_t)blockIdx.x * 256 + threadIdx.x;   // covers N_ROWS*D
    float x = f[i];
    __half h = __float2half_rn(x);
    g_fhi[i] = h;
    g_flo[i] = __float2half_rn(x - __half2float(h));
    if (i < (size_t)KSZ * D) {
        float y = Kc[i];
        __half hy = __float2half_rn(y);
        g_khi[i] = hy;
        g_klo[i] = __float2half_rn(y - __half2float(hy));
    }
}

// ---------------- kernel 2: code norms (fp32 exact) ----------------
__global__ void y2_kernel(const float* __restrict__ Kc) {
    int k = blockIdx.x;
    const float4* kv = (const float4*)(Kc + (size_t)k * D);
    float4 v = kv[threadIdx.x];
    float s = v.x * v.x + v.y * v.y + v.z * v.z + v.w * v.w;
    #pragma unroll
    for (int o = 16; o > 0; o >>= 1) s += __shfl_down_sync(0xffffffffu, s, o);
    __shared__ float sh[4];
    if ((threadIdx.x & 31) == 0) sh[threadIdx.x >> 5] = s;
    __syncthreads();
    if (threadIdx.x == 0) g_y2[k] = sh[0] + sh[1] + sh[2] + sh[3];
}

// ---------------- kernel 3: 3xFP16 mma.sync GEMM + argmin epilogue ----------------
// CTA tile 128 rows x 128 codes; 8 warps (4m x 2n) of 32x64; KBLK=16; 4 stages.
// 98KB smem/CTA -> 2 CTAs/SM (16 warps) so barrier bubbles of one CTA are
// covered by the other CTA's MMA work.
constexpr int KBLK   = 16;             // halves per k-block
constexpr int NKB    = D / KBLK;       // 32
constexpr int STAGES = 4;
constexpr int CODT   = KSZ / 128;      // 32 code tiles (inner for L2 reuse)

// smem stage layout in halves; row stride 24 halves (12 words: conflict-free,
// banks (12g+c) mod 32 all distinct for g<8, c<4)
constexpr int AH_H = 0;                // A hi: 128 x 24
constexpr int AL_H = 3072;             // A lo
constexpr int BH_H = 6144;             // B hi: 128 x 24
constexpr int BL_H = 9216;             // B lo
constexpr int STG_H = 12288;           // halves per stage
constexpr uint32_t STG_B = STG_H * 2;  // 24576 B
constexpr uint32_t SMEM_DYN = STAGES * STG_B;  // 98304 B

__global__ void __launch_bounds__(256, 2)
gemm_kernel() {
    extern __shared__ __half smem[];
    __shared__ unsigned long long best[128];
    __shared__ float sy2[128];

    const uint32_t sbase = smem_u32(smem);
    const int tid = threadIdx.x;
    const int wid = tid >> 5;
    const int lane = tid & 31;
    const int g = lane >> 2;        // groupID
    const int c = lane & 3;         // threadInGroup
    const int wm = wid & 3;         // 0..3 -> warp rows wm*32
    const int wn = wid >> 2;        // 0..1 -> warp cols wn*64
    const int wr = wm * 32;
    const int wc = wn * 64;

    const int codetile = blockIdx.x & (CODT - 1);
    const int rowtile  = blockIdx.x >> 5;
    const int row0  = rowtile * 128;
    const int code0 = codetile * 128;

    if (tid < 128) {
        best[tid] = ~0ULL;
        sy2[tid] = g_y2[code0 + tid];
    }

    const __half* fa_hi = g_fhi + (size_t)row0 * D;
    const __half* fa_lo = g_flo + (size_t)row0 * D;
    const __half* kb_hi = g_khi + (size_t)code0 * D;
    const __half* kb_lo = g_klo + (size_t)code0 * D;

    // stage fill: 4 cp.async(16B) per thread (one per matrix)
    const int fr = tid >> 1;            // row 0..127
    const int fk = (tid & 1) * 8;       // k offset in halves (0 or 8)
    auto fill = [&](int kb) {
        const uint32_t sb = sbase + (uint32_t)(kb & (STAGES - 1)) * STG_B;
        const uint32_t d = (uint32_t)(fr * 48 + fk * 2);   // bytes within split
        const size_t gsrc = (size_t)fr * D + kb * KBLK + fk;
        cp16(sb + AH_H * 2 + d, fa_hi + gsrc);
        cp16(sb + AL_H * 2 + d, fa_lo + gsrc);
        cp16(sb + BH_H * 2 + d, kb_hi + gsrc);
        cp16(sb + BL_H * 2 + d, kb_lo + gsrc);
        asm volatile("cp.async.commit_group;" ::: "memory");
    };

    fill(0);
    fill(1);
    fill(2);

    float acc[2][8][4];
    #pragma unroll
    for (int mt = 0; mt < 2; mt++)
        #pragma unroll
        for (int nt = 0; nt < 8; nt++)
            #pragma unroll
            for (int k = 0; k < 4; k++) acc[mt][nt][k] = 0.0f;

    for (int kb = 0; kb < NKB; kb++) {
        asm volatile("cp.async.wait_group 2;" ::: "memory");
        __syncthreads();
        // fill stage (kb+3)%4 == (kb-1)%4; safe: sync above released it
        if (kb + 3 < NKB) fill(kb + 3);

        const __half* S = smem + (size_t)(kb & (STAGES - 1)) * STG_H;
        const __half* Sah = S + AH_H;
        const __half* Sal = S + AL_H;
        const __half* Sbh = S + BH_H;
        const __half* Sbl = S + BL_H;

        uint32_t bh[8][2], bl[8][2];
        #pragma unroll
        for (int nt = 0; nt < 8; nt++) {
            const int n = wc + nt * 8 + g;
            bh[nt][0] = *(const uint32_t*)&Sbh[n * 24 + 2 * c];
            bh[nt][1] = *(const uint32_t*)&Sbh[n * 24 + 2 * c + 8];
            bl[nt][0] = *(const uint32_t*)&Sbl[n * 24 + 2 * c];
            bl[nt][1] = *(const uint32_t*)&Sbl[n * 24 + 2 * c + 8];
        }
        uint32_t ah[2][4], al[2][4];
        #pragma unroll
        for (int mt = 0; mt < 2; mt++) {
            const int r = wr + mt * 16 + g;
            ah[mt][0] = *(const uint32_t*)&Sah[r * 24 + 2 * c];
            ah[mt][1] = *(const uint32_t*)&Sah[(r + 8) * 24 + 2 * c];
            ah[mt][2] = *(const uint32_t*)&Sah[r * 24 + 2 * c + 8];
            ah[mt][3] = *(const uint32_t*)&Sah[(r + 8) * 24 + 2 * c + 8];
            al[mt][0] = *(const uint32_t*)&Sal[r * 24 + 2 * c];
            al[mt][1] = *(const uint32_t*)&Sal[(r + 8) * 24 + 2 * c];
            al[mt][2] = *(const uint32_t*)&Sal[r * 24 + 2 * c + 8];
            al[mt][3] = *(const uint32_t*)&Sal[(r + 8) * 24 + 2 * c + 8];
        }
        // term-major: independent accumulators between reuses
        #pragma unroll
        for (int mt = 0; mt < 2; mt++)
            #pragma unroll
            for (int nt = 0; nt < 8; nt++)
                mma16(acc[mt][nt], ah[mt], bh[nt]);   // hi*hi
        #pragma unroll
        for (int mt = 0; mt < 2; mt++)
            #pragma unroll
            for (int nt = 0; nt < 8; nt++)
                mma16(acc[mt][nt], ah[mt], bl[nt]);   // hi*lo
        #pragma unroll
        for (int mt = 0; mt < 2; mt++)
            #pragma unroll
            for (int nt = 0; nt < 8; nt++)
                mma16(acc[mt][nt], al[mt], bh[nt]);   // lo*hi
    }
    __syncthreads();

    // epilogue: per-row argmin over this CTA's 128 codes
    #pragma unroll
    for (int mt = 0; mt < 2; mt++) {
        #pragma unroll
        for (int half = 0; half < 2; half++) {
            const int r = wr + mt * 16 + g + half * 8;   // local row
            float bv = 3.4e38f; int bj = 0;
            #pragma unroll
            for (int nt = 0; nt < 8; nt++) {
                #pragma unroll
                for (int j = 0; j < 2; j++) {
                    const int col = wc + nt * 8 + c * 2 + j;
                    const float sc = sy2[col] - 2.0f * acc[mt][nt][half * 2 + j];
                    if (sc < bv) { bv = sc; bj = col; }
                }
            }
            const unsigned long long pk =
                ((unsigned long long)fkey(bv) << 32) | (unsigned)(code0 + bj);
            atomicMin(&best[r], pk);
        }
    }
    __syncthreads();
    if (tid < 128) atomicMin(&g_best[row0 + tid], best[tid]);
}

// ---------------- kernel 4: gather + loss + EMA scatter ----------------
__global__ void gather_kernel(const float* __restrict__ f, const float* __restrict__ Kc,
                              float* __restrict__ out) {
    const int row = blockIdx.x * 2 + (threadIdx.x >> 7);
    const int c4  = threadIdx.x & 127;
    const int idx = (int)(unsigned)(g_best[row] & 0xFFFFFFFFULL);
    float4 kv = __ldg((const float4*)(Kc + (size_t)idx * D) + c4);
    float4 fv = __ldg((const float4*)(f + (size_t)row * D) + c4);
    ((float4*)(out + OFF_F))[(size_t)row * (D / 4) + c4] = kv;
    float dx = kv.x - fv.x, dy = kv.y - fv.y, dz = kv.z - fv.z, dw_ = kv.w - fv.w;
    float s = dx * dx + dy * dy + dz * dz + dw_ * dw_;
    float* dwp = g_dw + (size_t)idx * D + c4 * 4;
    atomicAdd(dwp + 0, fv.x);
    atomicAdd(dwp + 1, fv.y);
    atomicAdd(dwp + 2, fv.z);
    atomicAdd(dwp + 3, fv.w);
    if (c4 == 0) atomicAdd(&g_counts[idx], 1.0f);
    #pragma unroll
    for (int o = 16; o > 0; o >>= 1) s += __shfl_down_sync(0xffffffffu, s, o);
    __shared__ float sh[8];
    if ((threadIdx.x & 31) == 0) sh[threadIdx.x >> 5] = s;
    __syncthreads();
    if (threadIdx.x == 0) {
        float tot = 0.0f;
        #pragma unroll
        for (int w = 0; w < 8; w++) tot += sh[w];
        atomicAdd(&g_loss, (double)tot);
    }
}

// ---------------- kernel 5: new_ecs + n ----------------
__global__ void ecs_kernel(const float* __restrict__ ecs, float* __restrict__ out) {
    const int i = blockIdx.x * 256 + threadIdx.x;
    float newc = ecs[i] * 0.99f + 0.01f * g_counts[i];
    out[OFF_ECS + i] = newc;
    float s = newc;
    #pragma unroll
    for (int o = 16; o > 0; o >>= 1) s += __shfl_down_sync(0xffffffffu, s, o);
    __shared__ float sh[8];
    if ((threadIdx.x & 31) == 0) sh[threadIdx.x >> 5] = s;
    __syncthreads();
    if (threadIdx.x == 0) {
        float tot = 0.0f;
        #pragma unroll
        for (int w = 0; w < 8; w++) tot += sh[w];
        atomicAdd(&g_n, (double)tot);
    }
}

// ---------------- kernel 6: new_ema_w, new_K, loss ----------------
__global__ void final_kernel(const float* __restrict__ emaw, float* __restrict__ out) {
    const size_t i = (size_t)blockIdx.x * 256 + threadIdx.x;
    const int k = (int)(i >> 9);   // D = 512
    float neww = emaw[i] * 0.99f + 0.01f * g_dw[i];
    out[OFF_EMAW + i] = neww;
    float nn = (float)g_n;
    float newc = out[OFF_ECS + k];
    float smoothed = (newc + 1e-5f) / (nn + 4096.0f * 1e-5f) * nn;
    out[OFF_K + i] = neww / smoothed;
    if (i == 0)
        out[OFF_LOSS] = (float)(g_loss / ((double)N_ROWS * (double)D));
}

extern "C" void kernel_launch(void* const* d_in, const int* in_sizes, int n_in,
                              void* d_out, int out_size) {
    const float* f    = (const float*)d_in[0];  // [8,4096,512]
    const float* Kc   = (const float*)d_in[1];  // [4096,512]
    const float* ecs  = (const float*)d_in[2];  // [4096]
    const float* emaw = (const float*)d_in[3];  // [4096,512]
    float* out = (float*)d_out;

    cudaFuncSetAttribute(gemm_kernel, cudaFuncAttributeMaxDynamicSharedMemorySize, SMEM_DYN);

    zero_kernel<<<(KSZ * D) / 256, 256>>>();
    split_kernel<<<(N_ROWS * D) / 256, 256>>>(f, Kc);
    y2_kernel<<<KSZ, 128>>>(Kc);
    gemm_kernel<<<(N_ROWS / 128) * CODT, 256, SMEM_DYN>>>();
    gather_kernel<<<N_ROWS / 2, 256>>>(f, Kc, out);
    ecs_kernel<<<KSZ / 256, 256>>>(ecs, out);
    final_kernel<<<(KSZ * D) / 256, 256>>>(emaw, out);
}